// round 11
// baseline (speedup 1.0000x reference)
#include <cuda_runtime.h>
#include <cstdint>
#include <cstddef>

#define FULLMASK 0xFFFFFFFFu
typedef unsigned long long u64;

constexpr int B  = 2048;
constexpr int T  = 256;
constexpr int NV = 32;

constexpr int   NSTEPS = 4;
constexpr float T_END  = 48.0f;

// ---- shared memory layout (float offsets) ----
constexpr int OFF_WIHRZ = 0;                     // [64][128] (r0,r1,z0,z1)/lane
constexpr int OFF_WIHN  = OFF_WIHRZ + 64*128;    // [64][64]  (n0,n1)/lane
constexpr int OFF_WHHRZ = OFF_WIHN  + 64*64;     // [64][128]
constexpr int OFF_WHHN  = OFF_WHHRZ + 64*128;    // [64][64]
constexpr int OFF_BIH   = OFF_WHHN  + 64*64;     // 192
constexpr int OFF_BHH   = OFF_BIH   + 192;       // 192
constexpr int OFF_WZ0T  = OFF_BHH   + 192;       // [64][64]
constexpr int OFF_BZ0   = OFF_WZ0T  + 64*64;     // 64
constexpr int OFF_W1T   = OFF_BZ0   + 64;        // [32][64]
constexpr int OFF_W2T   = OFF_W1T   + 32*64;     // [64][64]
constexpr int OFF_W3P   = OFF_W2T   + 64*64;     // [32][64]
constexpr int OFF_B1    = OFF_W3P   + 32*64;     // 64
constexpr int OFF_B2    = OFF_B1    + 64;        // 64
constexpr int OFF_B3    = OFF_B2    + 64;        // 32
constexpr int OFF_DW1T  = OFF_B3    + 32;        // [32][64]
constexpr int OFF_DB1   = OFF_DW1T  + 32*64;     // 64
constexpr int OFF_DW2   = OFF_DB1   + 64;        // 64
constexpr int OFF_DB2   = OFF_DW2   + 64;        // 1
// team/warp scratch
constexpr int OFF_XCHG  = ((OFF_DB2 + 4 + 3) & ~3); // 4 teams x 1024 (partial sums)
constexpr int OFF_HBUF  = OFF_XCHG + 4*1024;        // 4 teams x 512 (h dup, 4 elems)
constexpr int OFF_XSTG  = OFF_HBUF + 4*512;         // 8 warps x 256 (x inputs)
constexpr int OFF_OSCR  = OFF_XSTG + 8*256;         // 8 warps x 256 (ODE scratch)
constexpr int SMEM_FLOATS = OFF_OSCR + 8*256;
constexpr int SMEM_BYTES  = SMEM_FLOATS * 4;

__device__ float g_klpart[B];

__device__ __forceinline__ float tanh_f(float x) {
    float e = __expf(2.0f * x);
    return 1.0f - __fdividef(2.0f, e + 1.0f);
}
__device__ __forceinline__ float sig_f(float x) {
    return __fdividef(1.0f, 1.0f + __expf(-x));
}
__device__ __forceinline__ u64 pk2(float lo, float hi) {
    u64 r; asm("mov.b64 %0, {%1,%2};" : "=l"(r) : "f"(lo), "f"(hi)); return r;
}
__device__ __forceinline__ u64 dup2(float v) { return pk2(v, v); }
__device__ __forceinline__ float2 upk2(u64 v) {
    float2 r; asm("mov.b64 {%0,%1}, %2;" : "=f"(r.x), "=f"(r.y) : "l"(v)); return r;
}
__device__ __forceinline__ void ffma2(u64& acc, u64 w, u64 x) {
    asm("fma.rn.f32x2 %0, %1, %2, %0;" : "+l"(acc) : "l"(w), "l"(x));
}
__device__ __forceinline__ u64 fadd2(u64 a, u64 b) {
    u64 r; asm("add.rn.f32x2 %0, %1, %2;" : "=l"(r) : "l"(a), "l"(b)); return r;
}
__device__ __forceinline__ u64 lds2(const float* p) { return *(const u64*)p; }
__device__ __forceinline__ void teambar(int id) {
    asm volatile("bar.sync %0, %1;" :: "r"(id), "r"(64) : "memory");
}

__global__ void dummy_kernel() {}   // ncu launch-index alignment

__global__ void __launch_bounds__(256, 1)
latent_ode_kernel(const float* __restrict__ values,
                  const float* __restrict__ maskp,
                  const int*   __restrict__ seq_lengths,
                  const float* __restrict__ eps,
                  const float* __restrict__ W_ih,  const float* __restrict__ W_hh,
                  const float* __restrict__ b_ih,  const float* __restrict__ b_hh,
                  const float* __restrict__ W_z0,  const float* __restrict__ b_z0,
                  const float* __restrict__ ode_W1, const float* __restrict__ ode_b1,
                  const float* __restrict__ ode_W2, const float* __restrict__ ode_b2,
                  const float* __restrict__ ode_W3, const float* __restrict__ ode_b3,
                  const float* __restrict__ dec_W1, const float* __restrict__ dec_b1,
                  const float* __restrict__ dec_W2, const float* __restrict__ dec_b2,
                  float* __restrict__ out)
{
    extern __shared__ float s[];
    const int tid = threadIdx.x, nthr = blockDim.x;

    // ---- cooperative weight staging (runs once) ----
    for (int i = tid; i < 64*128; i += nthr) {
        int f = i >> 7, c = i & 127;
        int l = c >> 2, q = c & 3;
        int g = (q >> 1) * 64 + 2 * l + (q & 1);     // 0=r,1=z
        s[OFF_WIHRZ + i] = W_ih[g*64 + f];
    }
    for (int i = tid; i < 64*64; i += nthr) {
        int f = i >> 6, c = i & 63;
        s[OFF_WIHN + i] = W_ih[(128 + c)*64 + f];
    }
    for (int i = tid; i < 64*128; i += nthr) {
        int k = i >> 7, c = i & 127;
        int l = c >> 2, q = c & 3;
        int g = (q >> 1) * 64 + 2 * l + (q & 1);
        s[OFF_WHHRZ + i] = W_hh[g*64 + k];
    }
    for (int i = tid; i < 64*64; i += nthr) {
        int k = i >> 6, c = i & 63;
        s[OFF_WHHN + i] = W_hh[(128 + c)*64 + k];
    }
    for (int i = tid; i < 192;   i += nthr) { s[OFF_BIH + i] = b_ih[i]; s[OFF_BHH + i] = b_hh[i]; }
    for (int i = tid; i < 64*64; i += nthr) { int k = i / 64, j = i % 64; s[OFF_WZ0T + i] = W_z0[j*64 + k]; }
    for (int i = tid; i < 64;    i += nthr) s[OFF_BZ0 + i] = b_z0[i];
    for (int i = tid; i < 32*64; i += nthr) { int k = i / 64, j = i % 64; s[OFF_W1T + i] = ode_W1[j*32 + k]; }
    for (int i = tid; i < 64*64; i += nthr) { int j = i / 64, j2 = i % 64; s[OFF_W2T + i] = ode_W2[j2*64 + j]; }
    for (int i = tid; i < 64*32; i += nthr) {
        int j = i / 32, o = i % 32;
        s[OFF_W3P + (j >> 1) * 64 + 2 * o + (j & 1)] = ode_W3[o*64 + j];
    }
    for (int i = tid; i < 64;    i += nthr) { s[OFF_B1 + i] = ode_b1[i]; s[OFF_B2 + i] = ode_b2[i];
                                              s[OFF_DB1 + i] = dec_b1[i]; s[OFF_DW2 + i] = dec_W2[i]; }
    for (int i = tid; i < 32;    i += nthr) s[OFF_B3 + i] = ode_b3[i];
    for (int i = tid; i < 32*64; i += nthr) { int k = i / 64, j = i % 64; s[OFF_DW1T + i] = dec_W1[j*32 + k]; }
    if (tid == 0) s[OFF_DB2] = dec_b2[0];
    __syncthreads();

    const int wid  = tid >> 5;
    const int lane = tid & 31;
    const int half = wid & 1;          // 0: f,k in [0,32) + values; 1: [32,64) + mask
    const int team = wid >> 1;
    const int tbar = 1 + team;
    // team rank: SMSP pair (0,1) hosts teams {0,2}, (2,3) hosts {1,3};
    // ranks {0,3} vs {1,2} balance total sequence length per SMSP pair.
    const int rnk  = (team == 0) ? 0 : (team == 1) ? 1 : (team == 2) ? 3 : 2;
    const int Q = rnk * gridDim.x + blockIdx.x;
    if (Q >= B / 4) return;
    const int l2 = 2 * lane;

    const int xch = OFF_XCHG + team * 1024;
    const int hb  = OFF_HBUF + team * 512;
    const int xs  = OFF_XSTG + wid * 256;
    const int os  = OFF_OSCR + wid * 256;

    int len[4];
    #pragma unroll
    for (int e = 0; e < 4; ++e) len[e] = seq_lengths[4*Q + e];
    const int lmax = max(max(len[0], len[1]), max(len[2], len[3]));
    const int own0 = 2 * half;              // local gate-elems of this warp
    const int lenO0 = len[own0], lenO1 = len[own0 + 1];
    const int eA = 4*Q + own0, eB = eA + 1;

    // biases carried by half 0 only (appear once in the combined sums)
    const u64 bir = half ? 0ULL : lds2(&s[OFF_BIH + l2]);
    const u64 biz = half ? 0ULL : lds2(&s[OFF_BIH + 64 + l2]);
    const u64 bin = half ? 0ULL : lds2(&s[OFF_BIH + 128 + l2]);
    const u64 bhr = half ? 0ULL : lds2(&s[OFF_BHH + l2]);
    const u64 bhz = half ? 0ULL : lds2(&s[OFF_BHH + 64 + l2]);
    const u64 bhn = half ? 0ULL : lds2(&s[OFF_BHH + 128 + l2]);

    const float* xb[4];
    #pragma unroll
    for (int e = 0; e < 4; ++e)
        xb[e] = (half ? maskp : values) + (size_t)(4*Q + e) * T * NV;

    float hA0 = 0.0f, hA1 = 0.0f, hB0 = 0.0f, hB1 = 0.0f;   // own 2 elems

    // initial h staging (zeros) for own 2 elems
    { ulonglong2 z2; z2.x = 0ULL; z2.y = 0ULL;
      *(ulonglong2*)&s[hb + own0*128 + 4*lane] = z2;
      *(ulonglong2*)&s[hb + (own0+1)*128 + 4*lane] = z2; }
    teambar(tbar);

    // prefetch first input batch (own half only)
    float xin[4][2];
    #pragma unroll
    for (int e = 0; e < 4; ++e)
        #pragma unroll
        for (int tt = 0; tt < 2; ++tt)
            xin[e][tt] = (tt < len[e]) ? xb[e][(size_t)(T-1-tt)*NV + lane] : 0.0f;

    #pragma unroll 1
    for (int t0 = 0; t0 < lmax; t0 += 2) {
        // stage inputs (own half features), then prefetch next batch
        #pragma unroll
        for (int e = 0; e < 4; ++e) {
            s[xs + e*64 + lane]      = xin[e][0];
            s[xs + e*64 + 32 + lane] = xin[e][1];
        }
        __syncwarp();
        #pragma unroll
        for (int e = 0; e < 4; ++e)
            #pragma unroll
            for (int tt = 0; tt < 2; ++tt) {
                int t = t0 + 2 + tt;
                xin[e][tt] = (t < len[e]) ? xb[e][(size_t)(T-1-t)*NV + lane] : 0.0f;
            }

        // ---- x-GEMM over own f-half, 4 elems x 2 steps (partials) ----
        u64 xr[4][2], xz[4][2], xn[4][2];
        #pragma unroll
        for (int e = 0; e < 4; ++e) {
            xr[e][0] = bir; xr[e][1] = bir;
            xz[e][0] = biz; xz[e][1] = biz;
            xn[e][0] = bin; xn[e][1] = bin;
        }
        #pragma unroll 4
        for (int fl = 0; fl < 32; fl += 2) {
            const int f = half*32 + fl;
            ulonglong2 wi0 = *(const ulonglong2*)&s[OFF_WIHRZ + f*128 + 4*lane];
            u64 wn0 = lds2(&s[OFF_WIHN + f*64 + l2]);
            ulonglong2 wi1 = *(const ulonglong2*)&s[OFF_WIHRZ + (f+1)*128 + 4*lane];
            u64 wn1 = lds2(&s[OFF_WIHN + (f+1)*64 + l2]);
            #pragma unroll
            for (int e = 0; e < 4; ++e)
                #pragma unroll
                for (int tt = 0; tt < 2; ++tt) {
                    float2 xx = *(const float2*)&s[xs + e*64 + tt*32 + fl]; // broadcast
                    u64 d0 = dup2(xx.x), d1 = dup2(xx.y);
                    ffma2(xr[e][tt], wi0.x, d0); ffma2(xz[e][tt], wi0.y, d0); ffma2(xn[e][tt], wn0, d0);
                    ffma2(xr[e][tt], wi1.x, d1); ffma2(xz[e][tt], wi1.y, d1); ffma2(xn[e][tt], wn1, d1);
                }
        }

        // ---- two recurrent steps ----
        #pragma unroll
        for (int tt = 0; tt < 2; ++tt) {
            const int t = t0 + tt;
            if (t >= lmax) break;                         // uniform across team

            // h-GEMM over own k-half, 4 elems (partials)
            u64 hr[4], hz[4], hn[4];
            #pragma unroll
            for (int e = 0; e < 4; ++e) { hr[e] = bhr; hz[e] = bhz; hn[e] = bhn; }
            #pragma unroll 4
            for (int kl = 0; kl < 32; kl += 2) {
                const int k = half*32 + kl;
                ulonglong2 wh0 = *(const ulonglong2*)&s[OFF_WHHRZ + k*128 + 4*lane];
                u64 wn0 = lds2(&s[OFF_WHHN + k*64 + l2]);
                ulonglong2 wh1 = *(const ulonglong2*)&s[OFF_WHHRZ + (k+1)*128 + 4*lane];
                u64 wn1 = lds2(&s[OFF_WHHN + (k+1)*64 + l2]);
                #pragma unroll
                for (int e = 0; e < 4; ++e) {
                    ulonglong2 hd = *(const ulonglong2*)&s[hb + e*128 + 2*k];  // (dup h[k], dup h[k+1])
                    ffma2(hr[e], wh0.x, hd.x); ffma2(hz[e], wh0.y, hd.x); ffma2(hn[e], wn0, hd.x);
                    ffma2(hr[e], wh1.x, hd.y); ffma2(hz[e], wh1.y, hd.y); ffma2(hn[e], wn1, hd.y);
                }
            }

            // combined partials; exchange what the OTHER warp's gate-elems need
            u64 rs[4], zs[4];
            #pragma unroll
            for (int e = 0; e < 4; ++e) {
                rs[e] = fadd2(xr[e][tt], hr[e]);
                zs[e] = fadd2(xz[e][tt], hz[e]);
            }
            const int wrbase = xch + half*512;
            #pragma unroll
            for (int j = 0; j < 2; ++j) {
                const int eo = 2*(1-half) + j;
                *(u64*)&s[wrbase + j*256 +       2*lane] = rs[eo];
                *(u64*)&s[wrbase + j*256 +  64 + 2*lane] = zs[eo];
                *(u64*)&s[wrbase + j*256 + 128 + 2*lane] = xn[eo][tt];
                *(u64*)&s[wrbase + j*256 + 192 + 2*lane] = hn[eo];
            }
            teambar(tbar);

            // gates for own 2 elems (own partial + peer partial)
            const int rdbase = xch + (1-half)*512;
            {   // j = 0 -> elem own0 (state hA)
                u64 rT  = fadd2(rs[own0],      lds2(&s[rdbase +       2*lane]));
                u64 zT  = fadd2(zs[own0],      lds2(&s[rdbase +  64 + 2*lane]));
                u64 xnT = fadd2(xn[own0][tt],  lds2(&s[rdbase + 128 + 2*lane]));
                u64 hnT = fadd2(hn[own0],      lds2(&s[rdbase + 192 + 2*lane]));
                float2 rr = upk2(rT), zz = upk2(zT), xx = upk2(xnT), hh = upk2(hnT);
                float r0 = sig_f(rr.x), r1 = sig_f(rr.y);
                float z0 = sig_f(zz.x), z1 = sig_f(zz.y);
                float n0 = tanh_f(fmaf(r0, hh.x, xx.x));
                float n1 = tanh_f(fmaf(r1, hh.y, xx.y));
                float u0 = (1.0f - z0) * n0 + z0 * hA0;
                float u1 = (1.0f - z1) * n1 + z1 * hA1;
                if (t < lenO0) { hA0 = u0; hA1 = u1; }
            }
            {   // j = 1 -> elem own0+1 (state hB)
                u64 rT  = fadd2(rs[own0+1],     lds2(&s[rdbase + 256 +       2*lane]));
                u64 zT  = fadd2(zs[own0+1],     lds2(&s[rdbase + 256 +  64 + 2*lane]));
                u64 xnT = fadd2(xn[own0+1][tt], lds2(&s[rdbase + 256 + 128 + 2*lane]));
                u64 hnT = fadd2(hn[own0+1],     lds2(&s[rdbase + 256 + 192 + 2*lane]));
                float2 rr = upk2(rT), zz = upk2(zT), xx = upk2(xnT), hh = upk2(hnT);
                float r0 = sig_f(rr.x), r1 = sig_f(rr.y);
                float z0 = sig_f(zz.x), z1 = sig_f(zz.y);
                float n0 = tanh_f(fmaf(r0, hh.x, xx.x));
                float n1 = tanh_f(fmaf(r1, hh.y, xx.y));
                float u0 = (1.0f - z0) * n0 + z0 * hB0;
                float u1 = (1.0f - z1) * n1 + z1 * hB1;
                if (t < lenO1) { hB0 = u0; hB1 = u1; }
            }

            // stage new h (own 2 elems, dup format)
            { ulonglong2 t2; t2.x = dup2(hA0); t2.y = dup2(hA1);
              *(ulonglong2*)&s[hb + own0*128 + 4*lane] = t2; }
            { ulonglong2 t2; t2.x = dup2(hB0); t2.y = dup2(hB1);
              *(ulonglong2*)&s[hb + (own0+1)*128 + 4*lane] = t2; }
            teambar(tbar);
        }
    }

    // =====================  z0 head + KL partial (own 2 elems) ================
    float mAc = s[OFF_BZ0 + lane], lvAc = s[OFF_BZ0 + 32 + lane];
    float mBc = mAc,               lvBc = lvAc;
    #pragma unroll
    for (int k = 0; k < 64; ++k) {
        float hkA = __shfl_sync(FULLMASK, (k & 1) ? hA1 : hA0, k >> 1);
        float hkB = __shfl_sync(FULLMASK, (k & 1) ? hB1 : hB0, k >> 1);
        float wm = s[OFF_WZ0T + k * 64 + lane];
        float wl = s[OFF_WZ0T + k * 64 + 32 + lane];
        mAc  = fmaf(wm, hkA, mAc);   lvAc = fmaf(wl, hkA, lvAc);
        mBc  = fmaf(wm, hkB, mBc);   lvBc = fmaf(wl, hkB, lvBc);
    }
    float yA = fmaf(eps[(size_t)eA * 32 + lane], __expf(0.5f * lvAc), mAc);
    float yB = fmaf(eps[(size_t)eB * 32 + lane], __expf(0.5f * lvBc), mBc);

    float klA = 1.0f + lvAc - mAc * mAc - __expf(lvAc);
    float klB = 1.0f + lvBc - mBc * mBc - __expf(lvBc);
    #pragma unroll
    for (int o = 16; o > 0; o >>= 1) {
        klA += __shfl_xor_sync(FULLMASK, klA, o);
        klB += __shfl_xor_sync(FULLMASK, klB, o);
    }
    if (lane == 0) { g_klpart[eA] = klA; g_klpart[eB] = klB; }

    // =====================  fixed-step RK4 ODE (per warp, own 2 elems) ========
    const u64 bb1 = lds2(&s[OFF_B1 + l2]);
    const u64 bb2 = lds2(&s[OFF_B2 + l2]);
    const float b3v = s[OFF_B3 + lane];
    const float hstep = T_END / (float)NSTEPS;

    #pragma unroll 1
    for (int st = 0; st < NSTEPS; ++st) {
        float ytA = yA, ytB = yB, accA = 0.0f, accB = 0.0f;
        #pragma unroll 1
        for (int sub = 0; sub < 4; ++sub) {
            __syncwarp();
            *(u64*)&s[os +      2*lane] = dup2(ytA);
            *(u64*)&s[os + 64 + 2*lane] = dup2(ytB);
            __syncwarp();

            u64 aA = bb1, aB = bb1;
            #pragma unroll
            for (int k = 0; k < 32; k += 2) {
                ulonglong2 za = *(const ulonglong2*)&s[os + 2*k];
                ulonglong2 zb = *(const ulonglong2*)&s[os + 64 + 2*k];
                u64 w0 = lds2(&s[OFF_W1T + k*64 + l2]);
                u64 w1 = lds2(&s[OFF_W1T + (k+1)*64 + l2]);
                ffma2(aA, w0, za.x); ffma2(aA, w1, za.y);
                ffma2(aB, w0, zb.x); ffma2(aB, w1, zb.y);
            }
            float2 fa = upk2(aA), fb = upk2(aB);
            float aA0 = tanh_f(fa.x), aA1 = tanh_f(fa.y);
            float aB0 = tanh_f(fb.x), aB1 = tanh_f(fb.y);

            __syncwarp();
            { ulonglong2 as_; as_.x = dup2(aA0); as_.y = dup2(aA1);
              *(ulonglong2*)&s[os + 4*lane] = as_; }
            { ulonglong2 as_; as_.x = dup2(aB0); as_.y = dup2(aB1);
              *(ulonglong2*)&s[os + 128 + 4*lane] = as_; }
            __syncwarp();

            u64 cA = bb2, cB = bb2;
            #pragma unroll
            for (int j = 0; j < 64; j += 2) {
                ulonglong2 ja = *(const ulonglong2*)&s[os + 2*j];
                ulonglong2 jb = *(const ulonglong2*)&s[os + 128 + 2*j];
                u64 w0 = lds2(&s[OFF_W2T + j*64 + l2]);
                u64 w1 = lds2(&s[OFF_W2T + (j+1)*64 + l2]);
                ffma2(cA, w0, ja.x); ffma2(cA, w1, ja.y);
                ffma2(cB, w0, jb.x); ffma2(cB, w1, jb.y);
            }
            float2 fc = upk2(cA), fd = upk2(cB);
            float cA0 = tanh_f(fc.x), cA1 = tanh_f(fc.y);
            float cB0 = tanh_f(fd.x), cB1 = tanh_f(fd.y);

            __syncwarp();
            { ulonglong2 cs_; cs_.x = dup2(cA0); cs_.y = dup2(cA1);
              *(ulonglong2*)&s[os + 4*lane] = cs_; }
            { ulonglong2 cs_; cs_.x = dup2(cB0); cs_.y = dup2(cB1);
              *(ulonglong2*)&s[os + 128 + 4*lane] = cs_; }
            __syncwarp();

            float kvA = b3v, kvB = b3v;
            #pragma unroll
            for (int j = 0; j < 64; j += 2) {
                ulonglong2 ca = *(const ulonglong2*)&s[os + 2*j];
                ulonglong2 cb = *(const ulonglong2*)&s[os + 128 + 2*j];
                float2 wp = *(const float2*)&s[OFF_W3P + (j >> 1)*64 + 2*lane];
                float cj0A = upk2(ca.x).x, cj1A = upk2(ca.y).x;
                float cj0B = upk2(cb.x).x, cj1B = upk2(cb.y).x;
                kvA = fmaf(wp.x, cj0A, kvA); kvA = fmaf(wp.y, cj1A, kvA);
                kvB = fmaf(wp.x, cj0B, kvB); kvB = fmaf(wp.y, cj1B, kvB);
            }

            float wgt = (sub == 0 || sub == 3) ? 1.0f : 2.0f;
            accA = fmaf(wgt, kvA, accA);
            accB = fmaf(wgt, kvB, accB);
            float cc = (sub == 2) ? hstep : 0.5f * hstep;
            ytA = fmaf(cc, kvA, yA);
            ytB = fmaf(cc, kvB, yB);
        }
        yA = fmaf(hstep * (1.0f / 6.0f), accA, yA);
        yB = fmaf(hstep * (1.0f / 6.0f), accB, yB);
    }

    // =====================  decoder -> logits  =====================
    u64 dA = lds2(&s[OFF_DB1 + l2]), dB = dA;
    #pragma unroll
    for (int k = 0; k < 32; ++k) {
        float zA = __shfl_sync(FULLMASK, yA, k);
        float zB = __shfl_sync(FULLMASK, yB, k);
        u64 w = lds2(&s[OFF_DW1T + k * 64 + l2]);
        ffma2(dA, w, dup2(zA));
        ffma2(dB, w, dup2(zB));
    }
    float2 ra = upk2(dA), rb = upk2(dB);
    float2 w2 = *(const float2*)&s[OFF_DW2 + l2];
    float pA = fmaxf(ra.x, 0.0f) * w2.x + fmaxf(ra.y, 0.0f) * w2.y;
    float pB = fmaxf(rb.x, 0.0f) * w2.x + fmaxf(rb.y, 0.0f) * w2.y;
    #pragma unroll
    for (int o = 16; o > 0; o >>= 1) {
        pA += __shfl_xor_sync(FULLMASK, pA, o);
        pB += __shfl_xor_sync(FULLMASK, pB, o);
    }
    if (lane == 0) {
        float bo = s[OFF_DB2];
        out[eA] = pA + bo;
        out[eB] = pB + bo;
    }
}

__global__ void finalize_kernel(float* __restrict__ out, int out_size)
{
    __shared__ float red[256];
    float sacc = 0.0f;
    for (int i = threadIdx.x; i < B; i += 256) sacc += g_klpart[i];
    red[threadIdx.x] = sacc;
    __syncthreads();
    #pragma unroll
    for (int st = 128; st > 0; st >>= 1) {
        if (threadIdx.x < st) red[threadIdx.x] += red[threadIdx.x + st];
        __syncthreads();
    }
    if (threadIdx.x == 0 && out_size > B)
        out[B] = -0.5f * red[0] / (float)(B * 32);
}

extern "C" void kernel_launch(void* const* d_in, const int* in_sizes, int n_in,
                              void* d_out, int out_size)
{
    const float* values = (const float*)d_in[1];
    const float* maskp  = (const float*)d_in[2];
    const int*   seq    = (const int*)  d_in[3];
    const float* eps    = (const float*)d_in[4];
    const float* W_ih   = (const float*)d_in[5];
    const float* W_hh   = (const float*)d_in[6];
    const float* b_ih   = (const float*)d_in[7];
    const float* b_hh   = (const float*)d_in[8];
    const float* W_z0   = (const float*)d_in[9];
    const float* b_z0   = (const float*)d_in[10];
    const float* oW1    = (const float*)d_in[11];
    const float* ob1    = (const float*)d_in[12];
    const float* oW2    = (const float*)d_in[13];
    const float* ob2    = (const float*)d_in[14];
    const float* oW3    = (const float*)d_in[15];
    const float* ob3    = (const float*)d_in[16];
    const float* dW1    = (const float*)d_in[17];
    const float* db1    = (const float*)d_in[18];
    const float* dW2    = (const float*)d_in[19];
    const float* db2    = (const float*)d_in[20];
    float* out = (float*)d_out;

    cudaFuncSetAttribute(latent_ode_kernel,
                         cudaFuncAttributeMaxDynamicSharedMemorySize, SMEM_BYTES);

    // same launch pattern as R9 (ncu landed on latent_ode_kernel)
    dummy_kernel<<<1, 32>>>();
    dummy_kernel<<<1, 32>>>();
    dummy_kernel<<<1, 32>>>();
    latent_ode_kernel<<<148, 256, SMEM_BYTES>>>(
        values, maskp, seq, eps, W_ih, W_hh, b_ih, b_hh, W_z0, b_z0,
        oW1, ob1, oW2, ob2, oW3, ob3, dW1, db1, dW2, db2, out);
    finalize_kernel<<<1, 256>>>(out, out_size);
}

// round 12
// speedup vs baseline: 1.1464x; 1.1464x over previous
#include <cuda_runtime.h>
#include <cstdint>
#include <cstddef>

#define FULLMASK 0xFFFFFFFFu
typedef unsigned long long u64;

constexpr int B  = 2048;
constexpr int T  = 256;
constexpr int NV = 32;

constexpr int   NSTEPS = 4;
constexpr float T_END  = 48.0f;

// ---- shared memory layout (float offsets) ----
constexpr int OFF_WIHRZ = 0;                     // [64][128] (r0,r1,z0,z1)/lane
constexpr int OFF_WIHN  = OFF_WIHRZ + 64*128;    // [64][64]  (n0,n1)/lane
constexpr int OFF_WHHRZ = OFF_WIHN  + 64*64;     // [64][128]
constexpr int OFF_WHHN  = OFF_WHHRZ + 64*128;    // [64][64]
constexpr int OFF_BIH   = OFF_WHHN  + 64*64;     // 192
constexpr int OFF_BHH   = OFF_BIH   + 192;       // 192
constexpr int OFF_WZ0T  = OFF_BHH   + 192;       // [64][64]
constexpr int OFF_BZ0   = OFF_WZ0T  + 64*64;     // 64
constexpr int OFF_W1T   = OFF_BZ0   + 64;        // [32][64]
constexpr int OFF_W2T   = OFF_W1T   + 32*64;     // [64][64]
constexpr int OFF_W3P   = OFF_W2T   + 64*64;     // [32][64]
constexpr int OFF_B1    = OFF_W3P   + 32*64;     // 64
constexpr int OFF_B2    = OFF_B1    + 64;        // 64
constexpr int OFF_B3    = OFF_B2    + 64;        // 32
constexpr int OFF_DW1T  = OFF_B3    + 32;        // [32][64]
constexpr int OFF_DB1   = OFF_DW1T  + 32*64;     // 64
constexpr int OFF_DW2   = OFF_DB1   + 64;        // 64
constexpr int OFF_DB2   = OFF_DW2   + 64;        // 4
// per-warp stage (1024 floats): x_A [4 tt][64] @0, x_B @256, h_A dup @512, h_B dup @640
constexpr int OFF_STAGE = ((OFF_DB2 + 4 + 3) & ~3);
constexpr int SMEM_FLOATS = OFF_STAGE + 8*1024;
constexpr int SMEM_BYTES  = SMEM_FLOATS * 4;

__device__ float g_klpart[B];

__device__ __forceinline__ float tanh_f(float x) {
    float e = __expf(2.0f * x);
    return 1.0f - __fdividef(2.0f, e + 1.0f);
}
__device__ __forceinline__ float sig_f(float x) {
    return __fdividef(1.0f, 1.0f + __expf(-x));
}
__device__ __forceinline__ u64 pk2(float lo, float hi) {
    u64 r; asm("mov.b64 %0, {%1,%2};" : "=l"(r) : "f"(lo), "f"(hi)); return r;
}
__device__ __forceinline__ u64 dup2(float v) { return pk2(v, v); }
__device__ __forceinline__ float2 upk2(u64 v) {
    float2 r; asm("mov.b64 {%0,%1}, %2;" : "=f"(r.x), "=f"(r.y) : "l"(v)); return r;
}
__device__ __forceinline__ void ffma2(u64& acc, u64 w, u64 x) {
    asm("fma.rn.f32x2 %0, %1, %2, %0;" : "+l"(acc) : "l"(w), "l"(x));
}
__device__ __forceinline__ u64 lds2(const float* p) { return *(const u64*)p; }

__global__ void dummy_kernel() {}   // ncu launch-index alignment

__global__ void __launch_bounds__(256, 1)
latent_ode_kernel(const float* __restrict__ values,
                  const float* __restrict__ maskp,
                  const int*   __restrict__ seq_lengths,
                  const float* __restrict__ eps,
                  const float* __restrict__ W_ih,  const float* __restrict__ W_hh,
                  const float* __restrict__ b_ih,  const float* __restrict__ b_hh,
                  const float* __restrict__ W_z0,  const float* __restrict__ b_z0,
                  const float* __restrict__ ode_W1, const float* __restrict__ ode_b1,
                  const float* __restrict__ ode_W2, const float* __restrict__ ode_b2,
                  const float* __restrict__ ode_W3, const float* __restrict__ ode_b3,
                  const float* __restrict__ dec_W1, const float* __restrict__ dec_b1,
                  const float* __restrict__ dec_W2, const float* __restrict__ dec_b2,
                  float* __restrict__ out)
{
    extern __shared__ float s[];
    const int tid = threadIdx.x, nthr = blockDim.x;

    // ---- cooperative weight staging (runs once) ----
    for (int i = tid; i < 64*128; i += nthr) {
        int f = i >> 7, c = i & 127;
        int l = c >> 2, q = c & 3;
        int g = (q >> 1) * 64 + 2 * l + (q & 1);     // 0=r,1=z
        s[OFF_WIHRZ + i] = W_ih[g*64 + f];
    }
    for (int i = tid; i < 64*64; i += nthr) {
        int f = i >> 6, c = i & 63;
        s[OFF_WIHN + i] = W_ih[(128 + c)*64 + f];
    }
    for (int i = tid; i < 64*128; i += nthr) {
        int k = i >> 7, c = i & 127;
        int l = c >> 2, q = c & 3;
        int g = (q >> 1) * 64 + 2 * l + (q & 1);
        s[OFF_WHHRZ + i] = W_hh[g*64 + k];
    }
    for (int i = tid; i < 64*64; i += nthr) {
        int k = i >> 6, c = i & 63;
        s[OFF_WHHN + i] = W_hh[(128 + c)*64 + k];
    }
    for (int i = tid; i < 192;   i += nthr) { s[OFF_BIH + i] = b_ih[i]; s[OFF_BHH + i] = b_hh[i]; }
    for (int i = tid; i < 64*64; i += nthr) { int k = i / 64, j = i % 64; s[OFF_WZ0T + i] = W_z0[j*64 + k]; }
    for (int i = tid; i < 64;    i += nthr) s[OFF_BZ0 + i] = b_z0[i];
    for (int i = tid; i < 32*64; i += nthr) { int k = i / 64, j = i % 64; s[OFF_W1T + i] = ode_W1[j*32 + k]; }
    for (int i = tid; i < 64*64; i += nthr) { int j = i / 64, j2 = i % 64; s[OFF_W2T + i] = ode_W2[j2*64 + j]; }
    for (int i = tid; i < 64*32; i += nthr) {
        int j = i / 32, o = i % 32;
        s[OFF_W3P + (j >> 1) * 64 + 2 * o + (j & 1)] = ode_W3[o*64 + j];
    }
    for (int i = tid; i < 64;    i += nthr) { s[OFF_B1 + i] = ode_b1[i]; s[OFF_B2 + i] = ode_b2[i];
                                              s[OFF_DB1 + i] = dec_b1[i]; s[OFF_DW2 + i] = dec_W2[i]; }
    for (int i = tid; i < 32;    i += nthr) s[OFF_B3 + i] = ode_b3[i];
    for (int i = tid; i < 32*64; i += nthr) { int k = i / 64, j = i % 64; s[OFF_DW1T + i] = dec_W1[j*32 + k]; }
    if (tid == 0) s[OFF_DB2] = dec_b2[0];
    __syncthreads();

    const int wid  = tid >> 5;
    const int lane = tid & 31;
    const int ws   = OFF_STAGE + wid * 1024;
    const int rank = (wid < 4) ? wid : (11 - wid);       // snake per-SMSP balance
    const int P = rank * gridDim.x + blockIdx.x;
    if (P >= B / 2) return;
    const int eA = 2 * P, eB = 2 * P + 1;
    const int l2 = 2 * lane;

    const int lenA = seq_lengths[eA];
    const int lenB = seq_lengths[eB];
    const int lmax = max(lenA, lenB);

    const u64 bir = lds2(&s[OFF_BIH + l2]);
    const u64 biz = lds2(&s[OFF_BIH + 64 + l2]);
    const u64 bin = lds2(&s[OFF_BIH + 128 + l2]);
    const u64 bhr = lds2(&s[OFF_BHH + l2]);
    const u64 bhz = lds2(&s[OFF_BHH + 64 + l2]);
    const u64 bhn = lds2(&s[OFF_BHH + 128 + l2]);

    float hA0 = 0.0f, hA1 = 0.0f, hB0 = 0.0f, hB1 = 0.0f;

    const float* vbA = values + (size_t)eA * T * NV;
    const float* mbA = maskp  + (size_t)eA * T * NV;
    const float* vbB = values + (size_t)eB * T * NV;
    const float* mbB = maskp  + (size_t)eB * T * NV;

    // double-buffered global x loads (per batch of 4 steps)
    float nva[4], nma[4], nvb[4], nmb[4];
    #pragma unroll
    for (int tt = 0; tt < 4; ++tt) {
        int t = tt;
        nva[tt] = (t < lenA) ? vbA[(size_t)(T-1-t)*NV + lane] : 0.0f;
        nma[tt] = (t < lenA) ? mbA[(size_t)(T-1-t)*NV + lane] : 0.0f;
        nvb[tt] = (t < lenB) ? vbB[(size_t)(T-1-t)*NV + lane] : 0.0f;
        nmb[tt] = (t < lenB) ? mbB[(size_t)(T-1-t)*NV + lane] : 0.0f;
    }

    #pragma unroll 1
    for (int t0 = 0; t0 < lmax; t0 += 4) {
        // stage x (plain, conflict-free) from prefetched regs
        #pragma unroll
        for (int tt = 0; tt < 4; ++tt) {
            s[ws + tt*64 + lane]        = nva[tt];
            s[ws + tt*64 + 32 + lane]   = nma[tt];
            s[ws + 256 + tt*64 + lane]      = nvb[tt];
            s[ws + 256 + tt*64 + 32 + lane] = nmb[tt];
        }
        // prefetch next batch
        #pragma unroll
        for (int tt = 0; tt < 4; ++tt) {
            int t = t0 + 4 + tt;
            nva[tt] = (t < lenA) ? vbA[(size_t)(T-1-t)*NV + lane] : 0.0f;
            nma[tt] = (t < lenA) ? mbA[(size_t)(T-1-t)*NV + lane] : 0.0f;
            nvb[tt] = (t < lenB) ? vbB[(size_t)(T-1-t)*NV + lane] : 0.0f;
            nmb[tt] = (t < lenB) ? mbB[(size_t)(T-1-t)*NV + lane] : 0.0f;
        }
        __syncwarp();

        // ---- batched x-GEMM: 4 steps x 2 elems, xp stays in registers ----
        u64 xrA[4], xzA[4], xnA[4], xrB[4], xzB[4], xnB[4];
        #pragma unroll
        for (int tt = 0; tt < 4; ++tt) {
            xrA[tt] = bir; xzA[tt] = biz; xnA[tt] = bin;
            xrB[tt] = bir; xzB[tt] = biz; xnB[tt] = bin;
        }
        #pragma unroll 4
        for (int f = 0; f < 64; f += 2) {
            ulonglong2 wi0 = *(const ulonglong2*)&s[OFF_WIHRZ + f*128 + 4*lane];
            u64 wn0 = lds2(&s[OFF_WIHN + f*64 + l2]);
            ulonglong2 wi1 = *(const ulonglong2*)&s[OFF_WIHRZ + (f+1)*128 + 4*lane];
            u64 wn1 = lds2(&s[OFF_WIHN + (f+1)*64 + l2]);
            #pragma unroll
            for (int tt = 0; tt < 4; ++tt) {
                float2 xa = *(const float2*)&s[ws + tt*64 + f];        // (x[f], x[f+1]) broadcast
                float2 xb = *(const float2*)&s[ws + 256 + tt*64 + f];
                u64 da0 = dup2(xa.x), da1 = dup2(xa.y);
                u64 db0 = dup2(xb.x), db1 = dup2(xb.y);
                ffma2(xrA[tt], wi0.x, da0); ffma2(xzA[tt], wi0.y, da0); ffma2(xnA[tt], wn0, da0);
                ffma2(xrA[tt], wi1.x, da1); ffma2(xzA[tt], wi1.y, da1); ffma2(xnA[tt], wn1, da1);
                ffma2(xrB[tt], wi0.x, db0); ffma2(xzB[tt], wi0.y, db0); ffma2(xnB[tt], wn0, db0);
                ffma2(xrB[tt], wi1.x, db1); ffma2(xzB[tt], wi1.y, db1); ffma2(xnB[tt], wn1, db1);
            }
        }

        // ---- recurrent steps (h-GEMM + gates) ----
        #pragma unroll
        for (int tt = 0; tt < 4; ++tt) {
            int t = t0 + tt;
            if (t < lmax) {
                __syncwarp();
                { ulonglong2 hs; hs.x = dup2(hA0); hs.y = dup2(hA1);
                  *(ulonglong2*)&s[ws + 512 + 4*lane] = hs; }
                { ulonglong2 hs; hs.x = dup2(hB0); hs.y = dup2(hB1);
                  *(ulonglong2*)&s[ws + 640 + 4*lane] = hs; }
                __syncwarp();

                u64 hrA = bhr, hzA = bhz, hnA = bhn;
                u64 hrB = bhr, hzB = bhz, hnB = bhn;
                #pragma unroll 8
                for (int k = 0; k < 64; k += 2) {
                    ulonglong2 ha = *(const ulonglong2*)&s[ws + 512 + 2*k];
                    ulonglong2 hb = *(const ulonglong2*)&s[ws + 640 + 2*k];
                    ulonglong2 wh0 = *(const ulonglong2*)&s[OFF_WHHRZ + k*128 + 4*lane];
                    u64 wn0 = lds2(&s[OFF_WHHN + k*64 + l2]);
                    ulonglong2 wh1 = *(const ulonglong2*)&s[OFF_WHHRZ + (k+1)*128 + 4*lane];
                    u64 wn1 = lds2(&s[OFF_WHHN + (k+1)*64 + l2]);
                    ffma2(hrA, wh0.x, ha.x); ffma2(hzA, wh0.y, ha.x); ffma2(hnA, wn0, ha.x);
                    ffma2(hrB, wh0.x, hb.x); ffma2(hzB, wh0.y, hb.x); ffma2(hnB, wn0, hb.x);
                    ffma2(hrA, wh1.x, ha.y); ffma2(hzA, wh1.y, ha.y); ffma2(hnA, wn1, ha.y);
                    ffma2(hrB, wh1.x, hb.y); ffma2(hzB, wh1.y, hb.y); ffma2(hnB, wn1, hb.y);
                }

                {   // elem A gates
                    float2 xr = upk2(xrA[tt]), xz = upk2(xzA[tt]), xn = upk2(xnA[tt]);
                    float2 hr = upk2(hrA), hz = upk2(hzA), hn = upk2(hnA);
                    float r0  = sig_f(xr.x + hr.x), r1  = sig_f(xr.y + hr.y);
                    float z0  = sig_f(xz.x + hz.x), z1  = sig_f(xz.y + hz.y);
                    float n0  = tanh_f(fmaf(r0, hn.x, xn.x));
                    float n1  = tanh_f(fmaf(r1, hn.y, xn.y));
                    float u0  = (1.0f - z0) * n0 + z0 * hA0;
                    float u1  = (1.0f - z1) * n1 + z1 * hA1;
                    if (t < lenA) { hA0 = u0; hA1 = u1; }
                }
                {   // elem B gates
                    float2 xr = upk2(xrB[tt]), xz = upk2(xzB[tt]), xn = upk2(xnB[tt]);
                    float2 hr = upk2(hrB), hz = upk2(hzB), hn = upk2(hnB);
                    float r0  = sig_f(xr.x + hr.x), r1  = sig_f(xr.y + hr.y);
                    float z0  = sig_f(xz.x + hz.x), z1  = sig_f(xz.y + hz.y);
                    float n0  = tanh_f(fmaf(r0, hn.x, xn.x));
                    float n1  = tanh_f(fmaf(r1, hn.y, xn.y));
                    float u0  = (1.0f - z0) * n0 + z0 * hB0;
                    float u1  = (1.0f - z1) * n1 + z1 * hB1;
                    if (t < lenB) { hB0 = u0; hB1 = u1; }
                }
            }
        }
        __syncwarp();
    }

    // =====================  z0 head + KL partial  =====================
    float mAc = s[OFF_BZ0 + lane], lvAc = s[OFF_BZ0 + 32 + lane];
    float mBc = mAc,               lvBc = lvAc;
    #pragma unroll
    for (int k = 0; k < 64; ++k) {
        float hkA = __shfl_sync(FULLMASK, (k & 1) ? hA1 : hA0, k >> 1);
        float hkB = __shfl_sync(FULLMASK, (k & 1) ? hB1 : hB0, k >> 1);
        float wm = s[OFF_WZ0T + k * 64 + lane];
        float wl = s[OFF_WZ0T + k * 64 + 32 + lane];
        mAc  = fmaf(wm, hkA, mAc);   lvAc = fmaf(wl, hkA, lvAc);
        mBc  = fmaf(wm, hkB, mBc);   lvBc = fmaf(wl, hkB, lvBc);
    }
    float yA = fmaf(eps[(size_t)eA * 32 + lane], __expf(0.5f * lvAc), mAc);
    float yB = fmaf(eps[(size_t)eB * 32 + lane], __expf(0.5f * lvBc), mBc);

    float klA = 1.0f + lvAc - mAc * mAc - __expf(lvAc);
    float klB = 1.0f + lvBc - mBc * mBc - __expf(lvBc);
    #pragma unroll
    for (int o = 16; o > 0; o >>= 1) {
        klA += __shfl_xor_sync(FULLMASK, klA, o);
        klB += __shfl_xor_sync(FULLMASK, klB, o);
    }
    if (lane == 0) { g_klpart[eA] = klA; g_klpart[eB] = klB; }

    // =====================  fixed-step RK4 ODE  =====================
    const u64 bb1 = lds2(&s[OFF_B1 + l2]);
    const u64 bb2 = lds2(&s[OFF_B2 + l2]);
    const float b3v = s[OFF_B3 + lane];
    const float hstep = T_END / (float)NSTEPS;

    #pragma unroll 1
    for (int st = 0; st < NSTEPS; ++st) {
        float ytA = yA, ytB = yB, accA = 0.0f, accB = 0.0f;
        #pragma unroll 1
        for (int sub = 0; sub < 4; ++sub) {
            __syncwarp();
            *(u64*)&s[ws +      2*lane] = dup2(ytA);
            *(u64*)&s[ws + 64 + 2*lane] = dup2(ytB);
            __syncwarp();

            u64 aA = bb1, aB = bb1;
            #pragma unroll
            for (int k = 0; k < 32; k += 2) {
                ulonglong2 za = *(const ulonglong2*)&s[ws + 2*k];
                ulonglong2 zb = *(const ulonglong2*)&s[ws + 64 + 2*k];
                u64 w0 = lds2(&s[OFF_W1T + k*64 + l2]);
                u64 w1 = lds2(&s[OFF_W1T + (k+1)*64 + l2]);
                ffma2(aA, w0, za.x); ffma2(aA, w1, za.y);
                ffma2(aB, w0, zb.x); ffma2(aB, w1, zb.y);
            }
            float2 fa = upk2(aA), fb = upk2(aB);
            float aA0 = tanh_f(fa.x), aA1 = tanh_f(fa.y);
            float aB0 = tanh_f(fb.x), aB1 = tanh_f(fb.y);

            __syncwarp();
            { ulonglong2 as_; as_.x = dup2(aA0); as_.y = dup2(aA1);
              *(ulonglong2*)&s[ws + 4*lane] = as_; }
            { ulonglong2 as_; as_.x = dup2(aB0); as_.y = dup2(aB1);
              *(ulonglong2*)&s[ws + 128 + 4*lane] = as_; }
            __syncwarp();

            u64 cA = bb2, cB = bb2;
            #pragma unroll
            for (int j = 0; j < 64; j += 2) {
                ulonglong2 ja = *(const ulonglong2*)&s[ws + 2*j];
                ulonglong2 jb = *(const ulonglong2*)&s[ws + 128 + 2*j];
                u64 w0 = lds2(&s[OFF_W2T + j*64 + l2]);
                u64 w1 = lds2(&s[OFF_W2T + (j+1)*64 + l2]);
                ffma2(cA, w0, ja.x); ffma2(cA, w1, ja.y);
                ffma2(cB, w0, jb.x); ffma2(cB, w1, jb.y);
            }
            float2 fc = upk2(cA), fd = upk2(cB);
            float cA0 = tanh_f(fc.x), cA1 = tanh_f(fc.y);
            float cB0 = tanh_f(fd.x), cB1 = tanh_f(fd.y);

            __syncwarp();
            { ulonglong2 cs_; cs_.x = dup2(cA0); cs_.y = dup2(cA1);
              *(ulonglong2*)&s[ws + 4*lane] = cs_; }
            { ulonglong2 cs_; cs_.x = dup2(cB0); cs_.y = dup2(cB1);
              *(ulonglong2*)&s[ws + 128 + 4*lane] = cs_; }
            __syncwarp();

            float kvA = b3v, kvB = b3v;
            #pragma unroll
            for (int j = 0; j < 64; j += 2) {
                ulonglong2 ca = *(const ulonglong2*)&s[ws + 2*j];
                ulonglong2 cb = *(const ulonglong2*)&s[ws + 128 + 2*j];
                float2 wp = *(const float2*)&s[OFF_W3P + (j >> 1)*64 + 2*lane];
                float cj0A = upk2(ca.x).x, cj1A = upk2(ca.y).x;
                float cj0B = upk2(cb.x).x, cj1B = upk2(cb.y).x;
                kvA = fmaf(wp.x, cj0A, kvA); kvA = fmaf(wp.y, cj1A, kvA);
                kvB = fmaf(wp.x, cj0B, kvB); kvB = fmaf(wp.y, cj1B, kvB);
            }

            float wgt = (sub == 0 || sub == 3) ? 1.0f : 2.0f;
            accA = fmaf(wgt, kvA, accA);
            accB = fmaf(wgt, kvB, accB);
            float cc = (sub == 2) ? hstep : 0.5f * hstep;
            ytA = fmaf(cc, kvA, yA);
            ytB = fmaf(cc, kvB, yB);
        }
        yA = fmaf(hstep * (1.0f / 6.0f), accA, yA);
        yB = fmaf(hstep * (1.0f / 6.0f), accB, yB);
    }

    // =====================  decoder -> logits  =====================
    u64 dA = lds2(&s[OFF_DB1 + l2]), dB = dA;
    #pragma unroll
    for (int k = 0; k < 32; ++k) {
        float zA = __shfl_sync(FULLMASK, yA, k);
        float zB = __shfl_sync(FULLMASK, yB, k);
        u64 w = lds2(&s[OFF_DW1T + k * 64 + l2]);
        ffma2(dA, w, dup2(zA));
        ffma2(dB, w, dup2(zB));
    }
    float2 ra = upk2(dA), rb = upk2(dB);
    float2 w2 = *(const float2*)&s[OFF_DW2 + l2];
    float pA = fmaxf(ra.x, 0.0f) * w2.x + fmaxf(ra.y, 0.0f) * w2.y;
    float pB = fmaxf(rb.x, 0.0f) * w2.x + fmaxf(rb.y, 0.0f) * w2.y;
    #pragma unroll
    for (int o = 16; o > 0; o >>= 1) {
        pA += __shfl_xor_sync(FULLMASK, pA, o);
        pB += __shfl_xor_sync(FULLMASK, pB, o);
    }
    if (lane == 0) {
        float bo = s[OFF_DB2];
        out[eA] = pA + bo;
        out[eB] = pB + bo;
    }
}

__global__ void finalize_kernel(float* __restrict__ out, int out_size)
{
    __shared__ float red[256];
    float sacc = 0.0f;
    for (int i = threadIdx.x; i < B; i += 256) sacc += g_klpart[i];
    red[threadIdx.x] = sacc;
    __syncthreads();
    #pragma unroll
    for (int st = 128; st > 0; st >>= 1) {
        if (threadIdx.x < st) red[threadIdx.x] += red[threadIdx.x + st];
        __syncthreads();
    }
    if (threadIdx.x == 0 && out_size > B)
        out[B] = -0.5f * red[0] / (float)(B * 32);
}

extern "C" void kernel_launch(void* const* d_in, const int* in_sizes, int n_in,
                              void* d_out, int out_size)
{
    const float* values = (const float*)d_in[1];
    const float* maskp  = (const float*)d_in[2];
    const int*   seq    = (const int*)  d_in[3];
    const float* eps    = (const float*)d_in[4];
    const float* W_ih   = (const float*)d_in[5];
    const float* W_hh   = (const float*)d_in[6];
    const float* b_ih   = (const float*)d_in[7];
    const float* b_hh   = (const float*)d_in[8];
    const float* W_z0   = (const float*)d_in[9];
    const float* b_z0   = (const float*)d_in[10];
    const float* oW1    = (const float*)d_in[11];
    const float* ob1    = (const float*)d_in[12];
    const float* oW2    = (const float*)d_in[13];
    const float* ob2    = (const float*)d_in[14];
    const float* oW3    = (const float*)d_in[15];
    const float* ob3    = (const float*)d_in[16];
    const float* dW1    = (const float*)d_in[17];
    const float* db1    = (const float*)d_in[18];
    const float* dW2    = (const float*)d_in[19];
    const float* db2    = (const float*)d_in[20];
    float* out = (float*)d_out;

    cudaFuncSetAttribute(latent_ode_kernel,
                         cudaFuncAttributeMaxDynamicSharedMemorySize, SMEM_BYTES);

    // launch pattern that lands ncu (-s 5 -c 1) on latent_ode_kernel
    dummy_kernel<<<1, 32>>>();
    dummy_kernel<<<1, 32>>>();
    dummy_kernel<<<1, 32>>>();
    latent_ode_kernel<<<148, 256, SMEM_BYTES>>>(
        values, maskp, seq, eps, W_ih, W_hh, b_ih, b_hh, W_z0, b_z0,
        oW1, ob1, oW2, ob2, oW3, ob3, dW1, db1, dW2, db2, out);
    finalize_kernel<<<1, 256>>>(out, out_size);
}